// round 7
// baseline (speedup 1.0000x reference)
#include <cuda_runtime.h>
#include <cuda_fp16.h>
#include <cstdint>

// Problem constants (fixed by the dataset)
#define BROWS   32768
#define MDIM    512
#define HDIM    256
#define TOTROWS (2 * BROWS)   // both branches stacked

// ---------------------------------------------------------------------------
// Scratch (static device allocations — no cudaMalloc allowed)
// ---------------------------------------------------------------------------
__device__ __align__(16) __half   g_x16 [(size_t)BROWS * MDIM];   // f16(x)
__device__ __align__(16) uint16_t g_x8  [(size_t)BROWS * MDIM];   // (e4m3 hi, e4m3 lo*2^11)
__device__ __align__(16) __half   g_xc16[(size_t)BROWS * MDIM];
__device__ __align__(16) uint16_t g_xc8 [(size_t)BROWS * MDIM];
__device__ __align__(16) __half   g_a16_0[(size_t)TOTROWS * HDIM];
__device__ __align__(16) uint16_t g_a8_0 [(size_t)TOTROWS * HDIM];
__device__ __align__(16) __half   g_a16_1[(size_t)TOTROWS * HDIM];
__device__ __align__(16) uint16_t g_a8_1 [(size_t)TOTROWS * HDIM];
// Weights: fp16-hi fragment-major plane + fp8 digit fragment-major plane
__device__ __align__(16) uint32_t g_W16_0[(size_t)MDIM * 128];
__device__ __align__(16) uint32_t g_W16_H[5][(size_t)HDIM * 128];
__device__ __align__(16) uint32_t g_W8_0 [(size_t)MDIM * 128];
__device__ __align__(16) uint32_t g_W8_H [5][(size_t)HDIM * 128];

// ---------------------------------------------------------------------------
// Helpers
// ---------------------------------------------------------------------------
__device__ __forceinline__ uint32_t smem_u32(const void* p) {
    uint32_t a;
    asm("{ .reg .u64 t; cvta.to.shared.u64 t, %1; cvt.u32.u64 %0, t; }"
        : "=r"(a) : "l"(p));
    return a;
}
// fp16 in, f32 accum (main product)
__device__ __forceinline__ void mma_f16(float* d, const uint32_t* a,
                                        uint32_t b0, uint32_t b1) {
    asm volatile(
        "mma.sync.aligned.m16n8k16.row.col.f32.f16.f16.f32 "
        "{%0,%1,%2,%3}, {%4,%5,%6,%7}, {%8,%9}, {%0,%1,%2,%3};"
        : "+f"(d[0]), "+f"(d[1]), "+f"(d[2]), "+f"(d[3])
        : "r"(a[0]), "r"(a[1]), "r"(a[2]), "r"(a[3]), "r"(b0), "r"(b1));
}
// e4m3 in, f32 accum, k32 (correction products)
__device__ __forceinline__ void mma_e4m3(float* d, const uint32_t* a,
                                         uint32_t b0, uint32_t b1) {
    asm volatile(
        "mma.sync.aligned.m16n8k32.row.col.f32.e4m3.e4m3.f32 "
        "{%0,%1,%2,%3}, {%4,%5,%6,%7}, {%8,%9}, {%0,%1,%2,%3};"
        : "+f"(d[0]), "+f"(d[1]), "+f"(d[2]), "+f"(d[3])
        : "r"(a[0]), "r"(a[1]), "r"(a[2]), "r"(a[3]), "r"(b0), "r"(b1));
}
__device__ __forceinline__ void ldsm4(uint32_t* r, uint32_t addr) {
    asm volatile("ldmatrix.sync.aligned.m8n8.x4.shared.b16 {%0,%1,%2,%3}, [%4];"
                 : "=r"(r[0]), "=r"(r[1]), "=r"(r[2]), "=r"(r[3]) : "r"(addr));
}
#define CP_ASYNC16(dst, src) \
    asm volatile("cp.async.cg.shared.global [%0], [%1], 16;" :: "r"(dst), "l"(src))
#define CP_COMMIT() asm volatile("cp.async.commit_group;" ::: "memory")
#define CP_WAIT0()  asm volatile("cp.async.wait_group 0;" ::: "memory")

__device__ __forceinline__ uint32_t pack2h(__half a, __half b) {
    return (uint32_t)__half_as_ushort(a) |
           ((uint32_t)__half_as_ushort(b) << 16);
}
// u16 = (byte0 = e4m3(blo_val), byte1 = e4m3(bhi_val))  [a->hi byte, b->lo byte]
__device__ __forceinline__ uint16_t cvt2_e4m3(float hi_byte_val, float lo_byte_val) {
    uint16_t r;
    asm("cvt.rn.satfinite.e4m3x2.f32 %0, %1, %2;"
        : "=h"(r) : "f"(hi_byte_val), "f"(lo_byte_val));
    return r;
}
// element u16: byte0 = e4m3(v) [hi digit], byte1 = e4m3((v-f16(v))*2048) [lo digit]
__device__ __forceinline__ uint16_t a8_elem(float v, float rem) {
    return cvt2_e4m3(rem * 2048.0f, v);
}

// ---------------------------------------------------------------------------
// Corruption kernel (rank-q logic validated rel_err = 0.0 since R1);
// emits f16 plane + fp8 digit-pair plane for x and xc.
// ---------------------------------------------------------------------------
__global__ void __launch_bounds__(256) corrupt_kernel(
    const float* __restrict__ x, const float* __restrict__ u,
    const float* __restrict__ r, const float* __restrict__ low,
    const float* __restrict__ high, const int* __restrict__ qptr, int qdef,
    __half* __restrict__ x16, uint16_t* __restrict__ x8,
    __half* __restrict__ xc16, uint16_t* __restrict__ xc8)
{
    __shared__ float us[MDIM];
    __shared__ int   hist[1024];
    __shared__ int   s_bin, s_rank, s_cnt;
    __shared__ unsigned long long cand[48];
    __shared__ unsigned long long s_thresh;

    const int row = blockIdx.x;
    const int tid = threadIdx.x;
    const size_t base = (size_t)row * MDIM;

    int q = qptr ? *qptr : qdef;

    for (int j = tid; j < MDIM; j += 256) us[j] = u[base + j];
    for (int j = tid; j < 1024; j += 256) hist[j] = 0;
    __syncthreads();

    if (q <= 0) {
        if (tid == 0) s_thresh = 0ULL;
    } else if (q >= MDIM) {
        if (tid == 0) s_thresh = ~0ULL;
    }

    if (q > 0 && q < MDIM) {
        for (int j = tid; j < MDIM; j += 256) {
            float v = us[j];
            int b = (int)(v * 1024.0f);
            b = b < 0 ? 0 : (b > 1023 ? 1023 : b);
            atomicAdd(&hist[b], 1);
        }
        __syncthreads();

        if (tid < 32) {
            int s = 0;
            const int b0 = tid * 32;
            #pragma unroll
            for (int b = 0; b < 32; b++) s += hist[b0 + b];
            int pre = s;
            #pragma unroll
            for (int o = 1; o < 32; o <<= 1) {
                int n = __shfl_up_sync(0xffffffffu, pre, o);
                if (tid >= o) pre += n;
            }
            int excl = pre - s;
            if (q >= excl && q < excl + s) {
                int c = excl;
                for (int b = b0; b < b0 + 32; b++) {
                    int h = hist[b];
                    if (q < c + h) { s_bin = b; s_rank = q - c; break; }
                    c += h;
                }
            }
            if (tid == 0) s_cnt = 0;
        }
        __syncthreads();

        const int bsel = s_bin;
        for (int j = tid; j < MDIM; j += 256) {
            float v = us[j];
            int b = (int)(v * 1024.0f);
            b = b < 0 ? 0 : (b > 1023 ? 1023 : b);
            if (b == bsel) {
                int idx = atomicAdd(&s_cnt, 1);
                if (idx < 48)
                    cand[idx] = ((unsigned long long)__float_as_uint(v) << 9)
                                | (unsigned)j;
            }
        }
        __syncthreads();

        if (tid == 0) {
            int cnt = s_cnt < 48 ? s_cnt : 48;
            int rk = s_rank;
            unsigned long long th = 0ULL;
            for (int i = 0; i < cnt; i++) {
                int c = 0;
                for (int k2 = 0; k2 < cnt; k2++) c += (cand[k2] < cand[i]);
                if (c == rk) th = cand[i];
            }
            s_thresh = th;
        }
    }
    __syncthreads();

    const unsigned long long th = s_thresh;
    const int j0 = tid * 2, j1 = j0 + 1;
    float v0 = us[j0], v1 = us[j1];
    unsigned long long k0 =
        ((unsigned long long)__float_as_uint(v0) << 9) | (unsigned)j0;
    unsigned long long k1 =
        ((unsigned long long)__float_as_uint(v1) << 9) | (unsigned)j1;
    float xv0 = x[base + j0], xv1 = x[base + j1];
    float xr0 = low[j0] + (high[j0] - low[j0]) * r[base + j0];
    float xr1 = low[j1] + (high[j1] - low[j1]) * r[base + j1];
    float xc0 = (k0 < th) ? xr0 : xv0;
    float xc1 = (k1 < th) ? xr1 : xv1;

    __half h0 = __float2half_rn(xv0), h1 = __float2half_rn(xv1);
    float  rm0 = xv0 - __half2float(h0), rm1 = xv1 - __half2float(h1);
    *(uint32_t*)(x16 + base + j0) = pack2h(h0, h1);
    *(uint32_t*)(x8 + base + j0) =
        (uint32_t)a8_elem(xv0, rm0) | ((uint32_t)a8_elem(xv1, rm1) << 16);

    h0 = __float2half_rn(xc0); h1 = __float2half_rn(xc1);
    rm0 = xc0 - __half2float(h0); rm1 = xc1 - __half2float(h1);
    *(uint32_t*)(xc16 + base + j0) = pack2h(h0, h1);
    *(uint32_t*)(xc8 + base + j0) =
        (uint32_t)a8_elem(xc0, rm0) | ((uint32_t)a8_elem(xc1, rm1) << 16);
}

// ---------------------------------------------------------------------------
// Weight pack (fp16 hi plane, fragment-major; layout validated in R4-R6):
// u32 idx = (((c*2+ks)*16 + nfp)*32 + lane)*4 + ((nf&1)<<1 | b01)
// ---------------------------------------------------------------------------
__global__ void __launch_bounds__(256) pack_w16_kernel(
    const float* __restrict__ W, uint32_t* __restrict__ Wf, int K)
{
    int idx = blockIdx.x * 256 + threadIdx.x;   // over (K/2)*256
    if (idx >= (K / 2) * HDIM) return;
    int k2 = idx >> 8;
    int n  = idx & 255;
    int k  = k2 * 2;
    __half h0 = __float2half_rn(W[(size_t)k * HDIM + n]);
    __half h1 = __float2half_rn(W[(size_t)(k + 1) * HDIM + n]);

    int c = k >> 5, ks = (k >> 4) & 1, rem = k & 15;
    int b01 = rem >> 3, tig = (rem & 7) >> 1;
    int nf = n >> 3, nfp = nf >> 1;
    int reg4 = ((nf & 1) << 1) | b01;
    int lane = ((n & 7) << 2) | tig;
    size_t i32 = ((((size_t)c * 2 + ks) * 16 + nfp) * 32 + lane) * 4 + reg4;
    Wf[i32] = pack2h(h0, h1);
}

// ---------------------------------------------------------------------------
// Weight fp8 pack: digit fragment-major for m16n8k32 e4m3 B-fragments.
// u32 idx = ((c*32 + nf)*32 + lane)*4 + q, q: 0=hi r0, 1=hi r1, 2=lo r0, 3=lo r1
// reg r covers k = c*32 + r*16 + (lane&3)*4 + (0..3); col n = nf*8 + (lane>>2)
// lo digit pre-scaled by 2^11.
// ---------------------------------------------------------------------------
__global__ void __launch_bounds__(256) pack_w8_kernel(
    const float* __restrict__ W, uint32_t* __restrict__ W8, int K)
{
    int idx = blockIdx.x * 256 + threadIdx.x;   // over K*128
    if (idx >= K * 128) return;
    int q    = idx & 3;
    int lane = (idx >> 2) & 31;
    int nf   = (idx >> 7) & 31;
    int c    = idx >> 12;
    int r     = q & 1;
    int digit = q >> 1;    // 0 = hi, 1 = lo*2^11
    int n  = nf * 8 + (lane >> 2);
    int k0 = c * 32 + r * 16 + (lane & 3) * 4;

    float vals[4];
    #pragma unroll
    for (int j = 0; j < 4; j++) {
        float w = W[(size_t)(k0 + j) * HDIM + n];
        if (digit == 0) {
            vals[j] = w;
        } else {
            __half h = __float2half_rn(w);
            vals[j] = (w - __half2float(h)) * 2048.0f;
        }
    }
    uint16_t lo16 = cvt2_e4m3(vals[1], vals[0]);  // byte0 = vals[0]
    uint16_t hi16 = cvt2_e4m3(vals[3], vals[2]);
    W8[idx] = (uint32_t)lo16 | ((uint32_t)hi16 << 16);
}

// ---------------------------------------------------------------------------
// GEMM: C[128x64 tile of 256] = A @ W + bias.
// main: fp16 hi x fp16 hi -> f32 (2 HMMA / 32K)
// corr: e4m3 digits, shared 2^11 scale -> f32 (2 fp8 MMA k32 / 32K)
// 8 warps (4m x 2n), warp tile 32x32, double-buffered cp.async.
// ---------------------------------------------------------------------------
#define OFF_A16 0
#define OFF_A8  10240
#define OFF_B16 18432
#define OFF_B8  22528
#define STAGE_B 26624
#define DSMEM_SZ (2 * STAGE_B + 256)

template <int K, bool RELU, bool PACKOUT>
__global__ void __launch_bounds__(256, 2) gemm_hyb(
    const __half* __restrict__ A16, const uint16_t* __restrict__ A8,
    const __half* __restrict__ A216, const uint16_t* __restrict__ A28,
    int rowsA,
    const uint32_t* __restrict__ W16, const uint32_t* __restrict__ W8,
    const float* __restrict__ bias,
    __half* __restrict__ C16, uint16_t* __restrict__ C8,
    float* __restrict__ Cf)
{
    extern __shared__ __align__(16) char dsm[];
    const int tid  = threadIdx.x;
    const int lane = tid & 31;
    const int wid  = tid >> 5;
    const int wm   = wid >> 1;     // 0..3, 32 rows each
    const int wn   = wid & 1;      // 0..1, 32 cols each
    const int g8   = lane >> 2;
    const int tg   = lane & 3;

    const int row0 = blockIdx.y * 128;
    const int col0 = blockIdx.x * 64;
    const int nfp0 = blockIdx.x * 4;   // fp16 B nf-pairs
    const int nf0  = blockIdx.x * 8;   // fp8 B nf frags

    const uint32_t base = smem_u32(dsm);
    float* s_bias = (float*)(dsm + 2 * STAGE_B);

    const __half*   Ah = A16;
    const uint16_t* Aq = A8;
    int rb = row0;
    if (A216 != nullptr && row0 >= rowsA) { Ah = A216; Aq = A28; rb = row0 - rowsA; }
    const __half*   A16g = Ah + (size_t)rb * K;
    const uint16_t* A8g  = Aq + (size_t)rb * K;

    if (tid < 64) s_bias[tid] = bias[col0 + tid];

    const int NC = K / 32;

    auto issue = [&](int c, int buf) {
        const uint32_t sb = base + buf * STAGE_B;
        // A16: 128 rows x 32 f16 (64B data in 80B rows), 512 units
        #pragma unroll
        for (int i = 0; i < 2; i++) {
            int w = tid + i * 256;
            int m = w >> 2, uu = w & 3;
            CP_ASYNC16(sb + OFF_A16 + m * 80 + uu * 16,
                       A16g + (size_t)m * K + c * 32 + uu * 8);
        }
        // A8: 128 rows x 32 u16 (64B rows), XOR-swizzled units, 512 units
        #pragma unroll
        for (int i = 0; i < 2; i++) {
            int w = tid + i * 256;
            int m = w >> 2, uu = w & 3;
            CP_ASYNC16(sb + OFF_A8 + m * 64 + ((uu ^ (m & 3)) << 4),
                       A8g + (size_t)m * K + c * 32 + uu * 8);
        }
        // B16: 2 ks x (4 nfp x 32 lane) units = 256
        {
            int ks = tid >> 7, t = tid & 127;
            size_t gi = ((((size_t)c * 2 + ks) * 16 + nfp0 + (t >> 5)) * 32
                         + (t & 31)) * 4;
            CP_ASYNC16(sb + OFF_B16 + tid * 16, W16 + gi);
        }
        // B8: 8 nf x 32 lane units = 256
        {
            size_t gi = (((size_t)c * 32 + nf0 + (tid >> 5)) * 32 + (tid & 31)) * 4;
            CP_ASYNC16(sb + OFF_B8 + tid * 16, W8 + gi);
        }
    };

    issue(0, 0);
    CP_COMMIT();
    CP_WAIT0();
    __syncthreads();

    float accM[2][4][4];
    float accC[2][4][4];
    #pragma unroll
    for (int mi = 0; mi < 2; mi++)
        #pragma unroll
        for (int ni = 0; ni < 4; ni++)
            #pragma unroll
            for (int j = 0; j < 4; j++) { accM[mi][ni][j] = 0.0f; accC[mi][ni][j] = 0.0f; }

    const uint32_t laddr = (uint32_t)((lane & 15) * 80 + (lane >> 4) * 16);

    for (int c = 0; c < NC; c++) {
        const int cur = c & 1;
        if (c + 1 < NC) { issue(c + 1, cur ^ 1); CP_COMMIT(); }
        const uint32_t sb = base + cur * STAGE_B;

        // ---- main: fp16 hi x hi ----
        #pragma unroll
        for (int ks = 0; ks < 2; ks++) {
            uint32_t aHi[2][4];
            #pragma unroll
            for (int mi = 0; mi < 2; mi++) {
                const uint32_t tileOff =
                    (uint32_t)((wm * 32 + mi * 16) * 80 + ks * 32) + laddr;
                ldsm4(aHi[mi], sb + OFF_A16 + tileOff);
            }
            #pragma unroll
            for (int p2 = 0; p2 < 2; p2++) {
                const uint32_t boff =
                    (uint32_t)((ks * 128 + ((wn * 2 + p2) * 32 + lane)) * 16);
                uint32_t bv[4];
                asm volatile("ld.shared.v4.b32 {%0,%1,%2,%3}, [%4];"
                             : "=r"(bv[0]), "=r"(bv[1]), "=r"(bv[2]), "=r"(bv[3])
                             : "r"(sb + OFF_B16 + boff));
                #pragma unroll
                for (int h = 0; h < 2; h++) {
                    const int ni = p2 * 2 + h;
                    #pragma unroll
                    for (int mi = 0; mi < 2; mi++)
                        mma_f16(accM[mi][ni], aHi[mi], bv[h * 2], bv[h * 2 + 1]);
                }
            }
        }

        // ---- corrections: e4m3 k32 ----
        uint32_t a8h[2][4], a8l[2][4];
        #pragma unroll
        for (int mi = 0; mi < 2; mi++) {
            #pragma unroll
            for (int kh = 0; kh < 2; kh++) {
                #pragma unroll
                for (int ri = 0; ri < 2; ri++) {
                    int m = wm * 32 + mi * 16 + g8 + ri * 8;
                    uint32_t addr = sb + OFF_A8 + m * 64
                        + (((((tg >> 1) + kh * 2) ^ (g8 & 3)) << 4))
                        + ((tg & 1) << 3);
                    uint32_t w0, w1;
                    asm volatile("ld.shared.v2.b32 {%0,%1}, [%2];"
                                 : "=r"(w0), "=r"(w1) : "r"(addr));
                    a8h[mi][ri + 2 * kh] = __byte_perm(w0, w1, 0x6420);
                    a8l[mi][ri + 2 * kh] = __byte_perm(w0, w1, 0x7531);
                }
            }
        }
        #pragma unroll
        for (int ni = 0; ni < 4; ni++) {
            const uint32_t boff =
                (uint32_t)((((wn * 4 + ni) * 32 + lane)) * 16);
            uint32_t b8[4];   // {hi r0, hi r1, lo r0, lo r1}
            asm volatile("ld.shared.v4.b32 {%0,%1,%2,%3}, [%4];"
                         : "=r"(b8[0]), "=r"(b8[1]), "=r"(b8[2]), "=r"(b8[3])
                         : "r"(sb + OFF_B8 + boff));
            #pragma unroll
            for (int mi = 0; mi < 2; mi++) {
                mma_e4m3(accC[mi][ni], a8h[mi], b8[2], b8[3]);  // Ahi x Blo*2^11
                mma_e4m3(accC[mi][ni], a8l[mi], b8[0], b8[1]);  // Alo*2^11 x Bhi
            }
        }

        if (c + 1 < NC) { CP_WAIT0(); __syncthreads(); }
    }

    // ---- epilogue ----
    const float INV = 1.0f / 2048.0f;
    #pragma unroll
    for (int mi = 0; mi < 2; mi++) {
        const int m = row0 + wm * 32 + mi * 16 + g8;
        #pragma unroll
        for (int ni = 0; ni < 4; ni++) {
            const int nl = wn * 32 + ni * 8 + tg * 2;
            const float b0 = s_bias[nl], b1 = s_bias[nl + 1];
            float v0 = accM[mi][ni][0] + accC[mi][ni][0] * INV + b0;
            float v1 = accM[mi][ni][1] + accC[mi][ni][1] * INV + b1;
            float v2 = accM[mi][ni][2] + accC[mi][ni][2] * INV + b0;
            float v3 = accM[mi][ni][3] + accC[mi][ni][3] * INV + b1;
            if (RELU) {
                v0 = fmaxf(v0, 0.f); v1 = fmaxf(v1, 0.f);
                v2 = fmaxf(v2, 0.f); v3 = fmaxf(v3, 0.f);
            }
            const size_t i0 = (size_t)m * HDIM + col0 + nl;
            const size_t i1 = (size_t)(m + 8) * HDIM + col0 + nl;
            if (PACKOUT) {
                __half h0 = __float2half_rn(v0), h1 = __float2half_rn(v1);
                float  r0 = v0 - __half2float(h0), r1 = v1 - __half2float(h1);
                *(uint32_t*)(C16 + i0) = pack2h(h0, h1);
                *(uint32_t*)(C8 + i0) =
                    (uint32_t)a8_elem(v0, r0) | ((uint32_t)a8_elem(v1, r1) << 16);
                h0 = __float2half_rn(v2); h1 = __float2half_rn(v3);
                r0 = v2 - __half2float(h0); r1 = v3 - __half2float(h1);
                *(uint32_t*)(C16 + i1) = pack2h(h0, h1);
                *(uint32_t*)(C8 + i1) =
                    (uint32_t)a8_elem(v2, r0) | ((uint32_t)a8_elem(v3, r1) << 16);
            } else {
                *(float2*)(Cf + i0) = make_float2(v0, v1);
                *(float2*)(Cf + i1) = make_float2(v2, v3);
            }
        }
    }
}

// ---------------------------------------------------------------------------
// Launch
// ---------------------------------------------------------------------------
extern "C" void kernel_launch(void* const* d_in, const int* in_sizes, int n_in,
                              void* d_out, int out_size)
{
    const float *x = 0, *u = 0, *r = 0, *low = 0, *high = 0, *We0 = 0;
    const int* qptr = 0;
    const float* W65[8];  int nW = 0;
    const float* b256[8]; int nB = 0;

    for (int i = 0; i < n_in; i++) {
        int s = in_sizes[i];
        const float* p = (const float*)d_in[i];
        if (s == BROWS * MDIM) {
            if (!x) x = p; else if (!u) u = p; else if (!r) r = p;
        } else if (s == MDIM) {
            if (!low) low = p; else if (!high) high = p;
        } else if (s == 1) {
            qptr = (const int*)d_in[i];
        } else if (s == MDIM * HDIM) {
            We0 = p;
        } else if (s == HDIM * HDIM) {
            if (nW < 8) W65[nW++] = p;
        } else if (s == HDIM) {
            if (nB < 8) b256[nB++] = p;
        }
    }
    const float* bl[6] = {b256[0], b256[1], b256[2], b256[3], b256[4], b256[5]};

    __half *x16 = 0, *xc16 = 0, *a16_0 = 0, *a16_1 = 0;
    uint16_t *x8 = 0, *xc8 = 0, *a8_0 = 0, *a8_1 = 0;
    uint32_t *w16_0 = 0, *w16_H = 0, *w8_0 = 0, *w8_H = 0;
    cudaGetSymbolAddress((void**)&x16,   g_x16);
    cudaGetSymbolAddress((void**)&x8,    g_x8);
    cudaGetSymbolAddress((void**)&xc16,  g_xc16);
    cudaGetSymbolAddress((void**)&xc8,   g_xc8);
    cudaGetSymbolAddress((void**)&a16_0, g_a16_0);
    cudaGetSymbolAddress((void**)&a8_0,  g_a8_0);
    cudaGetSymbolAddress((void**)&a16_1, g_a16_1);
    cudaGetSymbolAddress((void**)&a8_1,  g_a8_1);
    cudaGetSymbolAddress((void**)&w16_0, g_W16_0);
    cudaGetSymbolAddress((void**)&w16_H, g_W16_H);
    cudaGetSymbolAddress((void**)&w8_0,  g_W8_0);
    cudaGetSymbolAddress((void**)&w8_H,  g_W8_H);
    float* out = (float*)d_out;

    const size_t WHPL = (size_t)HDIM * 128;
    auto w16 = [&](int i) { return w16_H + (size_t)i * WHPL; };
    auto w8  = [&](int i) { return w8_H + (size_t)i * WHPL; };

    cudaFuncSetAttribute(gemm_hyb<MDIM, true,  true >, cudaFuncAttributeMaxDynamicSharedMemorySize, DSMEM_SZ);
    cudaFuncSetAttribute(gemm_hyb<HDIM, true,  true >, cudaFuncAttributeMaxDynamicSharedMemorySize, DSMEM_SZ);
    cudaFuncSetAttribute(gemm_hyb<HDIM, false, true >, cudaFuncAttributeMaxDynamicSharedMemorySize, DSMEM_SZ);
    cudaFuncSetAttribute(gemm_hyb<HDIM, false, false>, cudaFuncAttributeMaxDynamicSharedMemorySize, DSMEM_SZ);

    // 1) corruption + plane emit
    corrupt_kernel<<<BROWS, 256>>>(x, u, r, low, high, qptr, 307,
                                   x16, x8, xc16, xc8);

    // 2) weight packing (tiny)
    pack_w16_kernel<<<(MDIM / 2 * HDIM) / 256, 256>>>(We0, w16_0, MDIM);
    pack_w8_kernel <<<(MDIM * 128) / 256, 256>>>(We0, w8_0, MDIM);
    for (int i = 0; i < 5; i++) {
        pack_w16_kernel<<<(HDIM / 2 * HDIM) / 256, 256>>>(W65[i], w16(i), HDIM);
        pack_w8_kernel <<<(HDIM * 128) / 256, 256>>>(W65[i], w8(i), HDIM);
    }

    // 3) 6 layers, fp16-main + fp8-correction tensor cores
    dim3 grid(HDIM / 64, TOTROWS / 128);   // (4, 512)
    dim3 blk(256);
    const __half* NH = (const __half*)0;
    const uint16_t* NQ = (const uint16_t*)0;

    gemm_hyb<MDIM, true,  true ><<<grid, blk, DSMEM_SZ>>>(
        x16, x8, xc16, xc8, BROWS, w16_0, w8_0, bl[0], a16_0, a8_0, (float*)0);
    gemm_hyb<HDIM, true,  true ><<<grid, blk, DSMEM_SZ>>>(
        a16_0, a8_0, NH, NQ, TOTROWS, w16(0), w8(0), bl[1], a16_1, a8_1, (float*)0);
    gemm_hyb<HDIM, true,  true ><<<grid, blk, DSMEM_SZ>>>(
        a16_1, a8_1, NH, NQ, TOTROWS, w16(1), w8(1), bl[2], a16_0, a8_0, (float*)0);
    gemm_hyb<HDIM, false, true ><<<grid, blk, DSMEM_SZ>>>(
        a16_0, a8_0, NH, NQ, TOTROWS, w16(2), w8(2), bl[3], a16_1, a8_1, (float*)0);
    gemm_hyb<HDIM, true,  true ><<<grid, blk, DSMEM_SZ>>>(
        a16_1, a8_1, NH, NQ, TOTROWS, w16(3), w8(3), bl[4], a16_0, a8_0, (float*)0);
    gemm_hyb<HDIM, false, false><<<grid, blk, DSMEM_SZ>>>(
        a16_0, a8_0, NH, NQ, TOTROWS, w16(4), w8(4), bl[5],
        (__half*)0, (uint16_t*)0, out);

    (void)out_size;
}